// round 2
// baseline (speedup 1.0000x reference)
#include <cuda_runtime.h>
#include <cstdint>

// Problem constants
#define T_LEN   730
#define B_LEN   1000
#define NMUL    8
#define LENF    15
#define NEARZERO 1e-5f

#define SCAN_BLOCKS 125          // 125*64 = 8000 chains
#define UH_BLOCKS   16           // 16*64 = 1024 >= 1000 basins
#define UG 10                    // timesteps per prefetch group
#define NGROUPS 73               // 73*10 = 730

// Scratch (device globals: allocation-free)
__device__ float g_qsurf[T_LEN * B_LEN];
__device__ float g_qgw  [T_LEN * B_LEN];
__device__ float g_uh   [B_LEN * LENF];

__device__ __forceinline__ float f_sqrt_approx(float x) {
    float r;
    asm("sqrt.approx.f32 %0, %1;" : "=f"(r) : "f"(x));
    return r;
}
__device__ __forceinline__ float f_ex2(float x) {
    float r;
    asm("ex2.approx.f32 %0, %1;" : "=f"(r) : "f"(x));
    return r;
}

// ---------------------------------------------------------------------------
// uh: gamma unit hydrograph weights for one basin (runs in extra blocks of the
// fused kernel, fully hidden behind the scan)
// ---------------------------------------------------------------------------
__device__ void uh_for_basin(const float* __restrict__ raw, int b) {
    float ra = raw[b * 34 + 32] * 2.9f;
    float rb = raw[b * 34 + 33] * 6.5f;
    float aa    = fmaxf(ra, 0.0f) + 0.1f;
    float theta = fmaxf(rb, 0.0f) + 0.5f;
    float lg   = lgammaf(aa);
    float lth  = logf(theta);
    float ivth = 1.0f / theta;
    float w[LENF];
    float s = 0.0f;
#pragma unroll
    for (int k = 0; k < LENF; ++k) {
        float t = (float)k + 0.5f;
        float lw = (aa - 1.0f) * logf(t) - t * ivth - lg - aa * lth;
        w[k] = expf(lw);
        s += w[k];
    }
    float inv = 1.0f / s;
#pragma unroll
    for (int k = 0; k < LENF; ++k)
        g_uh[b * LENF + k] = w[k] * inv;
}

// ---------------------------------------------------------------------------
// Fused kernel: blocks [0,125) run the abcd scan (1 chain/thread, 8 lanes per
// basin, reduce-scatter for the 5 cross-NMUL sums); blocks [125,141) compute
// the unit hydrograph concurrently.
// ---------------------------------------------------------------------------
struct ScanStep {
    // per-chain parameters (precomputed)
    float inv2a, binv2a, boa, nl2eob, onemc, c, d, inv1pd;
};

__global__ void __launch_bounds__(64) fused_scan_kernel(
    const float* __restrict__ x,      // (T,B,2)
    const float* __restrict__ raw,    // (B,34)
    float* __restrict__ out)          // (T,B,6)
{
    if (blockIdx.x >= SCAN_BLOCKS) {
        int b = (blockIdx.x - SCAN_BLOCKS) * 64 + threadIdx.x;
        if (b < B_LEN) uh_for_basin(raw, b);
        return;
    }

    int g  = blockIdx.x * 64 + threadIdx.x;   // 0..7999
    int b  = g >> 3;
    int m  = g & 7;

    float r0 = raw[b * 34 +      m];
    float r1 = raw[b * 34 +  8 + m];
    float r2 = raw[b * 34 + 16 + m];
    float r3 = raw[b * 34 + 24 + m];
    float a   = fmaf(r0, 0.9f, 0.1f);
    float bb  = fmaf(r1, 450.0f, 50.0f);
    float c   = r2;
    float d   = fmaf(r3, 0.89f, 0.01f);

    float inv2a  = 0.5f / a;
    float binv2a = bb * inv2a;
    float boa    = bb / a;
    float nl2eob = -1.44269504088896f / bb;   // -log2(e)/b
    float onemc  = 1.0f - c;
    float inv1pd = 1.0f / (1.0f + d);

    float S = 50.0f, G = 10.0f;

    // lane roles for reduce-scatter targets:
    //  m0 -> sum Qsurf, m1 -> sum Qgw, m2 -> sum AET, m4 -> sum S, m5 -> sum G
    bool lo = (m < 4);
    bool q2 = (m & 2) != 0;
    bool q1 = (m & 1) != 0;
    bool doStore = (m == 0) | (m == 1) | (m == 2) | (m == 4) | (m == 5);

    float* sp;
    long long sstride;
    if      (m == 0) { sp = g_qsurf + b;       sstride = B_LEN; }
    else if (m == 1) { sp = g_qgw   + b;       sstride = B_LEN; }
    else if (m == 2) { sp = out + b * 6 + 3;   sstride = 6 * B_LEN; }
    else if (m == 4) { sp = out + b * 6 + 4;   sstride = 6 * B_LEN; }
    else if (m == 5) { sp = out + b * 6 + 5;   sstride = 6 * B_LEN; }
    else             { sp = g_qsurf + b;       sstride = B_LEN; }   // inert

    const float2* __restrict__ xv = (const float2*)x;   // index t*B + b

    float2 bufA[UG], bufB[UG];

#define LOAD_GROUP(buf, grp) do {                                   \
        const float2* _base = xv + (grp) * UG * B_LEN + b;          \
        _Pragma("unroll")                                           \
        for (int _i = 0; _i < UG; ++_i) buf[_i] = __ldg(_base + _i * B_LEN); \
    } while (0)

#define STEP(pv, petv) do {                                         \
        float p   = (pv);                                           \
        float pet = (petv);                                         \
        float W    = p + S;                                         \
        float term = fmaf(W, inv2a, binv2a);                        \
        float wboa = W * boa;                                       \
        float arg  = fmaf(term, term, -wboa);                       \
        arg        = fmaxf(arg, NEARZERO);                          \
        float sq   = f_sqrt_approx(arg);                            \
        float Y    = term - sq;                                     \
        float ef   = f_ex2(pet * nl2eob);                           \
        float Snew = Y * ef;                                        \
        float avail = W - Y;                                        \
        float zqs   = onemc * avail;                                \
        float Gnew  = fmaf(c, avail, G) * inv1pd;                   \
        float zqg   = d * Gnew;                                     \
        float zaet  = Y - Snew;                                     \
        S = Snew; G = Gnew;                                         \
        /* reduce-scatter: 6 shfls deliver the 5 sums to lanes 0,1,2,4,5 */ \
        float s1 = lo ? Snew : zqs;                                 \
        float r1v = __shfl_xor_sync(0xffffffffu, s1, 4);            \
        float Aa  = (lo ? zqs : Snew) + r1v;                        \
        float s2 = lo ? Gnew : zqg;                                 \
        float r2v = __shfl_xor_sync(0xffffffffu, s2, 4);            \
        float Bb  = (lo ? zqg : Gnew) + r2v;                        \
        float r3v = __shfl_xor_sync(0xffffffffu, zaet, 4);          \
        float Cc  = zaet + r3v;                                     \
        float s4 = q2 ? Aa : Cc;                                    \
        float r4v = __shfl_xor_sync(0xffffffffu, s4, 2);            \
        Aa = q2 ? Aa : Aa + r4v;                                    \
        Cc = q2 ? Cc + r4v : Cc;                                    \
        float r5v = __shfl_xor_sync(0xffffffffu, Bb, 2);            \
        Bb = q2 ? Bb : Bb + r5v;                                    \
        float s6 = q2 ? Cc : (q1 ? Aa : Bb);                        \
        float r6v = __shfl_xor_sync(0xffffffffu, s6, 1);            \
        float fin = (q2 ? Cc : (q1 ? Bb : Aa)) + r6v;               \
        float v = fin * 0.125f;                                     \
        if (doStore) *sp = v;                                       \
        sp += sstride;                                              \
    } while (0)

    LOAD_GROUP(bufA, 0);

    for (int gi = 0; gi < NGROUPS; gi += 2) {
        if (gi + 1 < NGROUPS) LOAD_GROUP(bufB, gi + 1);
#pragma unroll
        for (int i = 0; i < UG; ++i) STEP(bufA[i].x, bufA[i].y);
        if (gi + 1 >= NGROUPS) break;
        if (gi + 2 < NGROUPS) LOAD_GROUP(bufA, gi + 2);
#pragma unroll
        for (int i = 0; i < UG; ++i) STEP(bufB[i].x, bufB[i].y);
    }
#undef STEP
#undef LOAD_GROUP
}

// ---------------------------------------------------------------------------
// Conv kernel: causal 15-tap convolution on Qsurf & Qgw; Qsim = sum (linear).
// Each thread: one basin, 10 consecutive t (730 = 73*10).
// ---------------------------------------------------------------------------
#define TPER 10
__global__ void conv_kernel(float* __restrict__ out) {
    int idx = blockIdx.x * blockDim.x + threadIdx.x;
    if (idx >= (T_LEN / TPER) * B_LEN) return;
    int b  = idx % B_LEN;
    int t0 = (idx / B_LEN) * TPER;

    float uh[LENF];
#pragma unroll
    for (int k = 0; k < LENF; ++k) uh[k] = __ldg(&g_uh[b * LENF + k]);

    float qs1[LENF - 1 + TPER];   // qsurf window: t0-14 .. t0+9
    float qs2[LENF - 1 + TPER];   // qgw window
#pragma unroll
    for (int i = 0; i < LENF - 1 + TPER; ++i) {
        int tt = t0 - (LENF - 1) + i;
        bool ok = (tt >= 0);
        qs1[i] = ok ? __ldg(&g_qsurf[tt * B_LEN + b]) : 0.0f;
        qs2[i] = ok ? __ldg(&g_qgw  [tt * B_LEN + b]) : 0.0f;
    }
#pragma unroll
    for (int j = 0; j < TPER; ++j) {
        float a1 = 0.0f, a2 = 0.0f;
#pragma unroll
        for (int k = 0; k < LENF; ++k) {
            a1 = fmaf(uh[k], qs1[LENF - 1 + j - k], a1);
            a2 = fmaf(uh[k], qs2[LENF - 1 + j - k], a2);
        }
        float* o = out + (t0 + j) * (6 * B_LEN) + b * 6;
        o[0] = a1 + a2;   // routed Qsim (conv is linear)
        o[1] = a1;        // routed Qsurf
        o[2] = a2;        // routed Qgw
    }
}

// ---------------------------------------------------------------------------
extern "C" void kernel_launch(void* const* d_in, const int* in_sizes, int n_in,
                              void* d_out, int out_size) {
    const float* x   = (const float*)d_in[0];   // (730,1000,2)
    const float* raw = (const float*)d_in[1];   // (1000,34)
    float* out = (float*)d_out;                 // (730,1000,6)

    fused_scan_kernel<<<SCAN_BLOCKS + UH_BLOCKS, 64>>>(x, raw, out);
    int nconv = (T_LEN / TPER) * B_LEN;
    conv_kernel<<<(nconv + 255) / 256, 256>>>(out);
}